// round 3
// baseline (speedup 1.0000x reference)
#include <cuda_runtime.h>
#include <cuda_bf16.h>
#include <cstdint>

#define MAXN 100000
#define MAXE 1600000
#define D    128
#define G    64
#define REP  32

// ---------------- device scratch (static: no runtime allocation) ----------------
__device__ float g_h1[MAXN * D];        // GEMM output (both layers)
__device__ float g_h2[MAXN * D];        // layer-1 activated output
__device__ int   g_deg[MAXN];
__device__ float g_dis[MAXN];
__device__ int   g_off[MAXN + 1];
__device__ int   g_cursor[MAXN];
__device__ int2  g_adj[MAXE];           // {src, bitcast(norm)}
__device__ int   g_cnt[G];
__device__ float g_gsum[G * REP];
__device__ int   g_is64;                // 1 if index inputs are int64, 0 if int32

// ---------------- index accessor (dtype-agnostic) ----------------
__device__ __forceinline__ int idx_at(const void* p, size_t i) {
    if (g_is64) return (int)((const long long*)p)[i];
    return ((const int*)p)[i];
}

// ---------------- dtype detection ----------------
// Edge values are node ids in [0, N) with N ~ 1e5, so if the buffer is int64
// (little-endian), every odd int32 word (high half) is 0. If int32, odd words
// are random node ids — all-zero over 16 samples is ~impossible.
__global__ void k_detect(const int* __restrict__ ei32) {
    if (threadIdx.x == 0) {
        int allz = 1;
        for (int i = 1; i < 32; i += 2)
            if (ei32[i] != 0) allz = 0;
        g_is64 = allz;
    }
}

// ---------------- init ----------------
__global__ void k_init(int n) {
    int i = blockIdx.x * blockDim.x + threadIdx.x;
    if (i < n) { g_deg[i] = 1; g_cursor[i] = 0; }
    if (i < G * REP) g_gsum[i] = 0.f;
    if (i < G) g_cnt[i] = 0;
}

// ---------------- degree count (in-degree via col = edge_index[1]) ----------------
__global__ void k_deg(const void* __restrict__ ei, int e) {
    int i = blockIdx.x * blockDim.x + threadIdx.x;
    if (i < e) {
        int c = idx_at(ei, (size_t)e + i);
        atomicAdd(&g_deg[c], 1);
    }
}

// ---------------- dis = rsqrt(deg); also graph node counts ----------------
__global__ void k_dis(const void* __restrict__ batch, int n) {
    int i = blockIdx.x * blockDim.x + threadIdx.x;
    if (i < n) {
        g_dis[i] = rsqrtf((float)g_deg[i]);
        atomicAdd(&g_cnt[idx_at(batch, i)], 1);
    }
}

// ---------------- single-block scan -> CSR offsets (counts = deg-1 = in-degree) ----------------
__global__ void k_scan(int n) {
    __shared__ int s[1024];
    const int T = 1024;
    int t = threadIdx.x;
    int ch = (n + T - 1) / T;
    int base = t * ch;
    int sum = 0;
    for (int i = 0; i < ch; i++) {
        int idx = base + i;
        if (idx < n) sum += g_deg[idx] - 1;
    }
    s[t] = sum;
    __syncthreads();
    for (int d = 1; d < T; d <<= 1) {
        int v = (t >= d) ? s[t - d] : 0;
        __syncthreads();
        s[t] += v;
        __syncthreads();
    }
    int run = s[t] - sum;      // exclusive prefix
    for (int i = 0; i < ch; i++) {
        int idx = base + i;
        if (idx < n) {
            g_off[idx] = run;
            run += g_deg[idx] - 1;
        }
    }
    if (t == 0) g_off[n] = s[T - 1];
}

// ---------------- fill CSR with (src, norm) ----------------
__global__ void k_fill(const void* __restrict__ ei, int e) {
    int i = blockIdx.x * blockDim.x + threadIdx.x;
    if (i < e) {
        int r = idx_at(ei, i);
        int c = idx_at(ei, (size_t)e + i);
        float w = g_dis[r] * g_dis[c];
        int pos = atomicAdd(&g_cursor[c], 1);
        g_adj[g_off[c] + pos] = make_int2(r, __float_as_int(w));
    }
}

// ---------------- GEMM: C[n x 128] = A[n x 128] @ W[128 x 128] ----------------
// Block: 256 threads, tile 64 rows x 128 cols, BK=32, thread tile 4x8.
#define BM 64
#define BK 32
__global__ void k_gemm(const float* __restrict__ A, const float* __restrict__ W,
                       float* __restrict__ Cout, int n) {
    __shared__ float As[BM][36];        // padded rows
    __shared__ float Ws[BK][D];
    int tid = threadIdx.x;
    int tx = tid & 15;                  // col group
    int ty = tid >> 4;                  // row group
    int row0 = blockIdx.x * BM;
    float acc[4][8];
#pragma unroll
    for (int r = 0; r < 4; r++)
#pragma unroll
        for (int j = 0; j < 8; j++) acc[r][j] = 0.f;

    for (int kb = 0; kb < D; kb += BK) {
        // load A tile (64 x 32), coalesced float4
#pragma unroll
        for (int l = 0; l < 2; l++) {
            int idx4 = tid + l * 256;          // 0..511 (64 rows * 8 float4)
            int m = idx4 >> 3;
            int k4 = idx4 & 7;
            float4 v = make_float4(0.f, 0.f, 0.f, 0.f);
            int gr = row0 + m;
            if (gr < n) v = *(const float4*)&A[(size_t)gr * D + kb + k4 * 4];
            *(float4*)&As[m][k4 * 4] = v;
        }
        // load W tile (32 x 128)
#pragma unroll
        for (int l = 0; l < 4; l++) {
            int idx4 = tid + l * 256;          // 0..1023 (32 rows * 32 float4)
            int k = idx4 >> 5;
            int n4 = idx4 & 31;
            *(float4*)&Ws[k][n4 * 4] = *(const float4*)&W[(size_t)(kb + k) * D + n4 * 4];
        }
        __syncthreads();
#pragma unroll
        for (int k = 0; k < BK; k++) {
            float a[4];
#pragma unroll
            for (int r = 0; r < 4; r++) a[r] = As[ty * 4 + r][k];
            float4 b0 = *(float4*)&Ws[k][tx * 4];
            float4 b1 = *(float4*)&Ws[k][64 + tx * 4];
            float bb[8] = {b0.x, b0.y, b0.z, b0.w, b1.x, b1.y, b1.z, b1.w};
#pragma unroll
            for (int r = 0; r < 4; r++)
#pragma unroll
                for (int j = 0; j < 8; j++) acc[r][j] += a[r] * bb[j];
        }
        __syncthreads();
    }
#pragma unroll
    for (int r = 0; r < 4; r++) {
        int row = row0 + ty * 4 + r;
        if (row < n) {
            float4 o0 = make_float4(acc[r][0], acc[r][1], acc[r][2], acc[r][3]);
            float4 o1 = make_float4(acc[r][4], acc[r][5], acc[r][6], acc[r][7]);
            *(float4*)&Cout[(size_t)row * D + tx * 4] = o0;
            *(float4*)&Cout[(size_t)row * D + 64 + tx * 4] = o1;
        }
    }
}

// ---------------- gather (warp per node). POOL=true fuses bias+leaky+fc-dot+pool ----------------
__device__ __forceinline__ float leaky(float x) { return x >= 0.f ? x : 0.01f * x; }

template <bool POOL>
__global__ void k_gather(const float4* __restrict__ hin, const float* __restrict__ bias,
                         const float* __restrict__ fcW, const void* __restrict__ batch,
                         float4* __restrict__ hout, int n) {
    int node = blockIdx.x * 4 + (threadIdx.x >> 5);
    if (node >= n) return;
    int lane = threadIdx.x & 31;

    float di = g_dis[node];
    float self = di * di;
    float4 acc = hin[(size_t)node * 32 + lane];
    acc.x *= self; acc.y *= self; acc.z *= self; acc.w *= self;

    int s = g_off[node], e = g_off[node + 1];
    int j = s;
    int2 a;
    if (j < e) a = g_adj[j];
    for (; j < e; j++) {
        int2 nx;
        if (j + 1 < e) nx = g_adj[j + 1];
        float w = __int_as_float(a.y);
        float4 hv = hin[(size_t)a.x * 32 + lane];
        acc.x += hv.x * w; acc.y += hv.y * w; acc.z += hv.z * w; acc.w += hv.w * w;
        a = nx;
    }
    float4 b = ((const float4*)bias)[lane];
    acc.x = leaky(acc.x + b.x);
    acc.y = leaky(acc.y + b.y);
    acc.z = leaky(acc.z + b.z);
    acc.w = leaky(acc.w + b.w);

    if (!POOL) {
        hout[(size_t)node * 32 + lane] = acc;
    } else {
        float4 f = ((const float4*)fcW)[lane];
        float d = acc.x * f.x + acc.y * f.y + acc.z * f.z + acc.w * f.w;
#pragma unroll
        for (int o = 16; o; o >>= 1) d += __shfl_down_sync(0xffffffffu, d, o);
        if (lane == 0) {
            int g = idx_at(batch, node);
            atomicAdd(&g_gsum[g * REP + (blockIdx.x & (REP - 1))], d);
        }
    }
}

// ---------------- final: out[g] = sum/cnt + fcb ----------------
__global__ void k_final(const float* __restrict__ fcb, float* __restrict__ out) {
    int g = threadIdx.x;
    if (g < G) {
        float s = 0.f;
#pragma unroll
        for (int r = 0; r < REP; r++) s += g_gsum[g * REP + r];
        float c = (float)g_cnt[g];
        if (c < 1.f) c = 1.f;
        out[g] = s / c + fcb[0];
    }
}

// ---------------- launch ----------------
extern "C" void kernel_launch(void* const* d_in, const int* in_sizes, int n_in,
                              void* d_out, int out_size) {
    const float* x    = (const float*)d_in[0];
    const void*  ei   = d_in[1];
    const void*  bat  = d_in[2];
    const float* W1   = (const float*)d_in[3];
    const float* b1   = (const float*)d_in[4];
    const float* W2   = (const float*)d_in[5];
    const float* b2   = (const float*)d_in[6];
    const float* fcW  = (const float*)d_in[7];
    const float* fcb  = (const float*)d_in[8];
    float*       out  = (float*)d_out;

    int n = in_sizes[0] / D;
    int e = in_sizes[1] / 2;

    float *h1, *h2;
    cudaGetSymbolAddress((void**)&h1, g_h1);
    cudaGetSymbolAddress((void**)&h2, g_h2);

    int tb = 256;
    k_detect<<<1, 32>>>((const int*)ei);
    k_init<<<(n + tb - 1) / tb, tb>>>(n);
    k_deg<<<(e + tb - 1) / tb, tb>>>(ei, e);
    k_dis<<<(n + tb - 1) / tb, tb>>>(bat, n);
    k_scan<<<1, 1024>>>(n);
    k_fill<<<(e + tb - 1) / tb, tb>>>(ei, e);

    // layer 1
    k_gemm<<<(n + BM - 1) / BM, 256>>>(x, W1, h1, n);
    k_gather<false><<<(n + 3) / 4, 128>>>((const float4*)h1, b1, nullptr, nullptr,
                                          (float4*)h2, n);
    // layer 2 (+ fused pooling/fc)
    k_gemm<<<(n + BM - 1) / BM, 256>>>(h2, W2, h1, n);
    k_gather<true><<<(n + 3) / 4, 128>>>((const float4*)h1, b2, fcW, bat,
                                         nullptr, n);

    k_final<<<1, G>>>(fcb, out);
}

// round 4
// speedup vs baseline: 1.4268x; 1.4268x over previous
#include <cuda_runtime.h>
#include <cstdint>

#define MAXN 100000
#define MAXE 1600000
#define D    128
#define G    64
#define REP  32
#define SCB  1024

// ---------------- device scratch ----------------
__device__ float g_h1[MAXN * D];
__device__ float g_h2[MAXN * D];
__device__ int   g_deg[MAXN];
__device__ float g_dis[MAXN];
__device__ int   g_off[MAXN + 1];
__device__ int   g_cursor[MAXN];
__device__ int2  g_adj[MAXE];           // {src, bitcast(norm)}
__device__ float g_gsum[G * REP];
__device__ int   g_bsum[128];
__device__ int   g_bbase[128];
__device__ int   g_is64;

// ---------------- dtype-agnostic index read ----------------
__device__ __forceinline__ int idx_at(const void* p, size_t i) {
    if (g_is64) return (int)((const long long*)p)[i];
    return ((const int*)p)[i];
}

// ---------------- init (+dtype detect by thread 0) ----------------
// If edge buffer is int64 (values < 2^31), every odd int32 word is 0.
__global__ void k_init(const int* __restrict__ ei32, int n) {
    int i = blockIdx.x * blockDim.x + threadIdx.x;
    if (i == 0) {
        int allz = 1;
        for (int j = 1; j < 32; j += 2)
            if (ei32[j] != 0) allz = 0;
        g_is64 = allz;
    }
    if (i < n) { g_deg[i] = 1; g_cursor[i] = 0; }
    if (i < G * REP) g_gsum[i] = 0.f;
}

// ---------------- in-degree count ----------------
__global__ void k_deg(const void* __restrict__ ei, int e) {
    int i = blockIdx.x * blockDim.x + threadIdx.x;
    if (i < e) atomicAdd(&g_deg[idx_at(ei, (size_t)e + i)], 1);
}

// ---------------- scan phase 1: block sums of (deg-1); also dis=rsqrt(deg) ----------------
__global__ void k_scan1(int n) {
    int i = blockIdx.x * SCB + threadIdx.x;
    int v = 0;
    if (i < n) {
        int d = g_deg[i];
        g_dis[i] = rsqrtf((float)d);
        v = d - 1;
    }
    int s = v;
#pragma unroll
    for (int o = 16; o; o >>= 1) s += __shfl_down_sync(0xffffffffu, s, o);
    __shared__ int ws[SCB / 32];
    int w = threadIdx.x >> 5, l = threadIdx.x & 31;
    if (l == 0) ws[w] = s;
    __syncthreads();
    if (w == 0) {
        int t = (l < SCB / 32) ? ws[l] : 0;
#pragma unroll
        for (int o = 16; o; o >>= 1) t += __shfl_down_sync(0xffffffffu, t, o);
        if (l == 0) g_bsum[blockIdx.x] = t;
    }
}

// ---------------- scan phase 2: exclusive scan of <=128 block sums ----------------
__global__ void k_scan2(int nb, int n) {
    __shared__ int sm[128];
    int t = threadIdx.x;
    int v = (t < nb) ? g_bsum[t] : 0;
    sm[t] = v;
    __syncthreads();
    for (int o = 1; o < 128; o <<= 1) {
        int u = (t >= o) ? sm[t - o] : 0;
        __syncthreads();
        if (t >= o) sm[t] += u;
        __syncthreads();
    }
    g_bbase[t] = sm[t] - v;     // exclusive
    if (t == 127) g_off[n] = sm[127];
}

// ---------------- scan phase 3: per-block exclusive scan -> g_off ----------------
__global__ void k_scan3(int n) {
    int i = blockIdx.x * SCB + threadIdx.x;
    int v = (i < n) ? (g_deg[i] - 1) : 0;
    int incl = v;
#pragma unroll
    for (int o = 1; o < 32; o <<= 1) {
        int u = __shfl_up_sync(0xffffffffu, incl, o);
        if ((threadIdx.x & 31) >= o) incl += u;
    }
    __shared__ int ws[SCB / 32];
    int w = threadIdx.x >> 5, l = threadIdx.x & 31;
    if (l == 31) ws[w] = incl;
    __syncthreads();
    if (w == 0) {
        int s = (l < SCB / 32) ? ws[l] : 0;
        int si = s;
#pragma unroll
        for (int o = 1; o < 32; o <<= 1) {
            int u = __shfl_up_sync(0xffffffffu, si, o);
            if (l >= o) si += u;
        }
        ws[l] = si - s;         // exclusive warp bases
    }
    __syncthreads();
    if (i < n) g_off[i] = g_bbase[blockIdx.x] + ws[w] + (incl - v);
}

// ---------------- fill CSR with (src, norm) ----------------
__global__ void k_fill(const void* __restrict__ ei, int e) {
    int i = blockIdx.x * blockDim.x + threadIdx.x;
    if (i < e) {
        int r = idx_at(ei, i);
        int c = idx_at(ei, (size_t)e + i);
        float w = g_dis[r] * g_dis[c];
        int pos = atomicAdd(&g_cursor[c], 1);
        g_adj[g_off[c] + pos] = make_int2(r, __float_as_int(w));
    }
}

// ---------------- GEMM: C[n x 128] = A[n x 128] @ W[128 x 128] ----------------
// 256 threads, tile 128x128, BK=16, 8x8 microtile.
#define BM 128
#define BK 16
__global__ __launch_bounds__(256, 2) void k_gemm(const float* __restrict__ A,
                                                 const float* __restrict__ W,
                                                 float* __restrict__ Cout, int n) {
    __shared__ float As[BM][BK + 1];
    __shared__ float Ws[BK][D];
    int tid = threadIdx.x;
    int tx = tid & 15;
    int ty = tid >> 4;
    int row0 = blockIdx.x * BM;
    float acc[8][8];
#pragma unroll
    for (int r = 0; r < 8; r++)
#pragma unroll
        for (int j = 0; j < 8; j++) acc[r][j] = 0.f;

    for (int kb = 0; kb < D; kb += BK) {
#pragma unroll
        for (int l = 0; l < 2; l++) {           // A tile 128x16 = 512 float4
            int idx4 = tid + l * 256;
            int m = idx4 >> 2, c4 = idx4 & 3;
            float4 v = make_float4(0.f, 0.f, 0.f, 0.f);
            int gr = row0 + m;
            if (gr < n) v = *(const float4*)&A[(size_t)gr * D + kb + c4 * 4];
            As[m][c4 * 4 + 0] = v.x; As[m][c4 * 4 + 1] = v.y;
            As[m][c4 * 4 + 2] = v.z; As[m][c4 * 4 + 3] = v.w;
        }
#pragma unroll
        for (int l = 0; l < 2; l++) {           // W tile 16x128 = 512 float4
            int idx4 = tid + l * 256;
            int k = idx4 >> 5, n4 = idx4 & 31;
            *(float4*)&Ws[k][n4 * 4] = *(const float4*)&W[(size_t)(kb + k) * D + n4 * 4];
        }
        __syncthreads();
#pragma unroll
        for (int k = 0; k < BK; k++) {
            float a[8], b[8];
#pragma unroll
            for (int r = 0; r < 8; r++) a[r] = As[ty * 8 + r][k];
            *(float4*)&b[0] = *(float4*)&Ws[k][tx * 8];
            *(float4*)&b[4] = *(float4*)&Ws[k][tx * 8 + 4];
#pragma unroll
            for (int r = 0; r < 8; r++)
#pragma unroll
                for (int j = 0; j < 8; j++) acc[r][j] += a[r] * b[j];
        }
        __syncthreads();
    }
#pragma unroll
    for (int r = 0; r < 8; r++) {
        int row = row0 + ty * 8 + r;
        if (row < n) {
            *(float4*)&Cout[(size_t)row * D + tx * 8] =
                make_float4(acc[r][0], acc[r][1], acc[r][2], acc[r][3]);
            *(float4*)&Cout[(size_t)row * D + tx * 8 + 4] =
                make_float4(acc[r][4], acc[r][5], acc[r][6], acc[r][7]);
        }
    }
}

// ---------------- gather (warp per node); POOL fuses bias+leaky+fc+pool ----------------
__device__ __forceinline__ float leaky(float x) { return x >= 0.f ? x : 0.01f * x; }

template <bool POOL>
__global__ void k_gather(const float4* __restrict__ hin, const float* __restrict__ bias,
                         const float* __restrict__ fcW, const void* __restrict__ batch,
                         float4* __restrict__ hout, int n) {
    int node = blockIdx.x * 4 + (threadIdx.x >> 5);
    if (node >= n) return;
    int lane = threadIdx.x & 31;

    float di = g_dis[node];
    float self = di * di;
    float4 acc = hin[(size_t)node * 32 + lane];
    acc.x *= self; acc.y *= self; acc.z *= self; acc.w *= self;

    int s = g_off[node], e = g_off[node + 1];
    int j = s;
    int2 a;
    if (j < e) a = g_adj[j];
    for (; j < e; j++) {
        int2 nx;
        if (j + 1 < e) nx = g_adj[j + 1];
        float w = __int_as_float(a.y);
        float4 hv = hin[(size_t)a.x * 32 + lane];
        acc.x += hv.x * w; acc.y += hv.y * w; acc.z += hv.z * w; acc.w += hv.w * w;
        a = nx;
    }
    float4 b = ((const float4*)bias)[lane];
    acc.x = leaky(acc.x + b.x);
    acc.y = leaky(acc.y + b.y);
    acc.z = leaky(acc.z + b.z);
    acc.w = leaky(acc.w + b.w);

    if (!POOL) {
        hout[(size_t)node * 32 + lane] = acc;
    } else {
        float4 f = ((const float4*)fcW)[lane];
        float d = acc.x * f.x + acc.y * f.y + acc.z * f.z + acc.w * f.w;
#pragma unroll
        for (int o = 16; o; o >>= 1) d += __shfl_down_sync(0xffffffffu, d, o);
        if (lane == 0) {
            int g = idx_at(batch, node);
            atomicAdd(&g_gsum[g * REP + (blockIdx.x & (REP - 1))], d);
        }
    }
}

// ---------------- final: counts via binary search over sorted batch ----------------
__global__ void k_final(const void* __restrict__ batch, const float* __restrict__ fcb,
                        float* __restrict__ out, int n) {
    __shared__ int lb[G + 1];
    int t = threadIdx.x;
    if (t <= G) {
        int lo = 0, hi = n;
        while (lo < hi) {
            int mid = (lo + hi) >> 1;
            if (idx_at(batch, mid) < t) lo = mid + 1; else hi = mid;
        }
        lb[t] = lo;
    }
    __syncthreads();
    if (t < G) {
        float s = 0.f;
#pragma unroll
        for (int r = 0; r < REP; r++) s += g_gsum[t * REP + r];
        float c = (float)(lb[t + 1] - lb[t]);
        if (c < 1.f) c = 1.f;
        out[t] = s / c + fcb[0];
    }
}

// ---------------- launch ----------------
extern "C" void kernel_launch(void* const* d_in, const int* in_sizes, int n_in,
                              void* d_out, int out_size) {
    const float* x    = (const float*)d_in[0];
    const void*  ei   = d_in[1];
    const void*  bat  = d_in[2];
    const float* W1   = (const float*)d_in[3];
    const float* b1   = (const float*)d_in[4];
    const float* W2   = (const float*)d_in[5];
    const float* b2   = (const float*)d_in[6];
    const float* fcW  = (const float*)d_in[7];
    const float* fcb  = (const float*)d_in[8];
    float*       out  = (float*)d_out;

    int n = in_sizes[0] / D;
    int e = in_sizes[1] / 2;
    int nb = (n + SCB - 1) / SCB;

    float *h1, *h2;
    cudaGetSymbolAddress((void**)&h1, g_h1);
    cudaGetSymbolAddress((void**)&h2, g_h2);

    static cudaStream_t s2 = nullptr;
    static cudaEvent_t ev_fork = nullptr, ev_join = nullptr;
    if (!s2) {
        cudaStreamCreateWithFlags(&s2, cudaStreamNonBlocking);
        cudaEventCreateWithFlags(&ev_fork, cudaEventDisableTiming);
        cudaEventCreateWithFlags(&ev_join, cudaEventDisableTiming);
    }

    int tb = 256;

    // fork: layer-1 GEMM depends only on x, W1 — runs parallel to CSR build
    cudaEventRecord(ev_fork, 0);
    cudaStreamWaitEvent(s2, ev_fork, 0);
    k_gemm<<<(n + BM - 1) / BM, 256, 0, s2>>>(x, W1, h1, n);
    cudaEventRecord(ev_join, s2);

    // CSR build on default stream
    k_init<<<(n + tb - 1) / tb, tb>>>((const int*)ei, n);
    k_deg<<<(e + tb - 1) / tb, tb>>>(ei, e);
    k_scan1<<<nb, SCB>>>(n);
    k_scan2<<<1, 128>>>(nb, n);
    k_scan3<<<nb, SCB>>>(n);
    k_fill<<<(e + tb - 1) / tb, tb>>>(ei, e);

    // join, then layer 1 aggregate
    cudaStreamWaitEvent(0, ev_join, 0);
    k_gather<false><<<(n + 3) / 4, 128>>>((const float4*)h1, b1, nullptr, nullptr,
                                          (float4*)h2, n);
    // layer 2 (+ fused pooling/fc)
    k_gemm<<<(n + BM - 1) / BM, 256>>>(h2, W2, h1, n);
    k_gather<true><<<(n + 3) / 4, 128>>>((const float4*)h1, b2, fcW, bat,
                                         nullptr, n);
    k_final<<<1, 128>>>(bat, fcb, out, n);
}

// round 5
// speedup vs baseline: 1.7626x; 1.2354x over previous
#include <cuda_runtime.h>
#include <cstdint>

#define MAXN 100000
#define MAXE 1600000
#define D    128
#define G    64
#define REP  32
#define SCB  1024
#define TM   64      // nodes per fused-kernel block

// ---------------- device scratch ----------------
__device__ float g_h2[MAXN * D];        // layer-1 output (only intermediate)
__device__ int   g_deg[MAXN];
__device__ float g_dis[MAXN];
__device__ int   g_off[MAXN + 1];
__device__ int   g_cursor[MAXN];
__device__ int2  g_adj[MAXE];           // {src, bitcast(norm)}
__device__ float g_gsum[G * REP];
__device__ int   g_bsum[128];
__device__ int   g_bbase[128];
__device__ int   g_is64;

// ---------------- dtype-agnostic index read ----------------
__device__ __forceinline__ int idx_at(const void* p, size_t i) {
    if (g_is64) return (int)((const long long*)p)[i];
    return ((const int*)p)[i];
}

// ---------------- init (+dtype detect) ----------------
__global__ void k_init(const int* __restrict__ ei32, int n) {
    int i = blockIdx.x * blockDim.x + threadIdx.x;
    if (i == 0) {
        int allz = 1;
        for (int j = 1; j < 32; j += 2)
            if (ei32[j] != 0) allz = 0;
        g_is64 = allz;
    }
    if (i < n) { g_deg[i] = 1; g_cursor[i] = 0; }
    if (i < G * REP) g_gsum[i] = 0.f;
}

// ---------------- in-degree count ----------------
__global__ void k_deg(const void* __restrict__ ei, int e) {
    int i = blockIdx.x * blockDim.x + threadIdx.x;
    if (i < e) atomicAdd(&g_deg[idx_at(ei, (size_t)e + i)], 1);
}

// ---------------- scan phase 1: block sums of (deg-1); also dis=rsqrt(deg) ----------------
__global__ void k_scan1(int n) {
    int i = blockIdx.x * SCB + threadIdx.x;
    int v = 0;
    if (i < n) {
        int d = g_deg[i];
        g_dis[i] = rsqrtf((float)d);
        v = d - 1;
    }
    int s = v;
#pragma unroll
    for (int o = 16; o; o >>= 1) s += __shfl_down_sync(0xffffffffu, s, o);
    __shared__ int ws[SCB / 32];
    int w = threadIdx.x >> 5, l = threadIdx.x & 31;
    if (l == 0) ws[w] = s;
    __syncthreads();
    if (w == 0) {
        int t = (l < SCB / 32) ? ws[l] : 0;
#pragma unroll
        for (int o = 16; o; o >>= 1) t += __shfl_down_sync(0xffffffffu, t, o);
        if (l == 0) g_bsum[blockIdx.x] = t;
    }
}

// ---------------- scan phase 2 ----------------
__global__ void k_scan2(int nb, int n) {
    __shared__ int sm[128];
    int t = threadIdx.x;
    int v = (t < nb) ? g_bsum[t] : 0;
    sm[t] = v;
    __syncthreads();
    for (int o = 1; o < 128; o <<= 1) {
        int u = (t >= o) ? sm[t - o] : 0;
        __syncthreads();
        if (t >= o) sm[t] += u;
        __syncthreads();
    }
    g_bbase[t] = sm[t] - v;
    if (t == 127) g_off[n] = sm[127];
}

// ---------------- scan phase 3 ----------------
__global__ void k_scan3(int n) {
    int i = blockIdx.x * SCB + threadIdx.x;
    int v = (i < n) ? (g_deg[i] - 1) : 0;
    int incl = v;
#pragma unroll
    for (int o = 1; o < 32; o <<= 1) {
        int u = __shfl_up_sync(0xffffffffu, incl, o);
        if ((threadIdx.x & 31) >= o) incl += u;
    }
    __shared__ int ws[SCB / 32];
    int w = threadIdx.x >> 5, l = threadIdx.x & 31;
    if (l == 31) ws[w] = incl;
    __syncthreads();
    if (w == 0) {
        int s = (l < SCB / 32) ? ws[l] : 0;
        int si = s;
#pragma unroll
        for (int o = 1; o < 32; o <<= 1) {
            int u = __shfl_up_sync(0xffffffffu, si, o);
            if (l >= o) si += u;
        }
        ws[l] = si - s;
    }
    __syncthreads();
    if (i < n) g_off[i] = g_bbase[blockIdx.x] + ws[w] + (incl - v);
}

// ---------------- fill CSR ----------------
__global__ void k_fill(const void* __restrict__ ei, int e) {
    int i = blockIdx.x * blockDim.x + threadIdx.x;
    if (i < e) {
        int r = idx_at(ei, i);
        int c = idx_at(ei, (size_t)e + i);
        float w = g_dis[r] * g_dis[c];
        int pos = atomicAdd(&g_cursor[c], 1);
        g_adj[g_off[c] + pos] = make_int2(r, __float_as_int(w));
    }
}

// ---------------- fused layer: agg(input) -> smem -> GEMM -> epilogue ----------------
// agg(in@W) == agg(in)@W  (aggregation is linear), so gather first, GEMM second.
__device__ __forceinline__ float leaky(float x) { return x >= 0.f ? x : 0.01f * x; }

template <int POOL>
__global__ __launch_bounds__(256, 2) void k_fused(
    const float4* __restrict__ in, const float* __restrict__ W,
    const float* __restrict__ bias, const float* __restrict__ fcW,
    const void* __restrict__ batch, float4* __restrict__ hout, int n)
{
    __shared__ float At[D][66];     // transposed agg tile: At[feature][node]
    __shared__ float Ws[16][D];
    __shared__ float rowsum[TM];

    int tid = threadIdx.x;
    int warp = tid >> 5, lane = tid & 31;
    int row0 = blockIdx.x * TM;

    // ---- phase 1: gather agg rows into smem (warp per node) ----
    for (int nd = warp; nd < TM; nd += 8) {
        int node = row0 + nd;
        float4 acc = make_float4(0.f, 0.f, 0.f, 0.f);
        if (node < n) {
            float di = g_dis[node];
            float self = di * di;
            float4 v = in[(size_t)node * 32 + lane];
            acc.x = v.x * self; acc.y = v.y * self;
            acc.z = v.z * self; acc.w = v.w * self;
            int s = g_off[node], e = g_off[node + 1];
            int j = s;
            int2 a;
            if (j < e) a = g_adj[j];
            for (; j < e; j++) {
                int2 nx;
                if (j + 1 < e) nx = g_adj[j + 1];
                float w = __int_as_float(a.y);
                float4 hv = in[(size_t)a.x * 32 + lane];
                acc.x += hv.x * w; acc.y += hv.y * w;
                acc.z += hv.z * w; acc.w += hv.w * w;
                a = nx;
            }
        }
        int c = lane * 4;
        At[c + 0][nd] = acc.x;
        At[c + 1][nd] = acc.y;
        At[c + 2][nd] = acc.z;
        At[c + 3][nd] = acc.w;
    }
    if (POOL && tid < TM) rowsum[tid] = 0.f;

    // ---- phase 2: GEMM  C[64x128] = At^T @ W, streaming W in 16-row slabs ----
    int tx = tid & 15;              // row group: rows tx*4 .. tx*4+3
    int ty = tid >> 4;              // col group: cols ty*8 .. ty*8+7
    float acc[4][8];
#pragma unroll
    for (int r = 0; r < 4; r++)
#pragma unroll
        for (int j = 0; j < 8; j++) acc[r][j] = 0.f;

    for (int kb = 0; kb < D; kb += 16) {
#pragma unroll
        for (int l = 0; l < 2; l++) {
            int idx4 = tid + l * 256;          // 512 float4 = 16x128 floats
            int k = idx4 >> 5, c4 = idx4 & 31;
            *(float4*)&Ws[k][c4 * 4] = *(const float4*)&W[(size_t)(kb + k) * D + c4 * 4];
        }
        __syncthreads();
#pragma unroll
        for (int k = 0; k < 16; k++) {
            float a[4], b[8];
#pragma unroll
            for (int r = 0; r < 4; r++) a[r] = At[kb + k][tx * 4 + r];
            *(float4*)&b[0] = *(float4*)&Ws[k][ty * 8];
            *(float4*)&b[4] = *(float4*)&Ws[k][ty * 8 + 4];
#pragma unroll
            for (int r = 0; r < 4; r++)
#pragma unroll
                for (int j = 0; j < 8; j++) acc[r][j] += a[r] * b[j];
        }
        __syncthreads();
    }

    // ---- phase 3: epilogue ----
    if (!POOL) {
#pragma unroll
        for (int r = 0; r < 4; r++) {
            int row = row0 + tx * 4 + r;
            if (row < n) {
                float4 o0, o1;
                o0.x = leaky(acc[r][0] + bias[ty * 8 + 0]);
                o0.y = leaky(acc[r][1] + bias[ty * 8 + 1]);
                o0.z = leaky(acc[r][2] + bias[ty * 8 + 2]);
                o0.w = leaky(acc[r][3] + bias[ty * 8 + 3]);
                o1.x = leaky(acc[r][4] + bias[ty * 8 + 4]);
                o1.y = leaky(acc[r][5] + bias[ty * 8 + 5]);
                o1.z = leaky(acc[r][6] + bias[ty * 8 + 6]);
                o1.w = leaky(acc[r][7] + bias[ty * 8 + 7]);
                hout[(size_t)row * 32 + ty * 2] = o0;
                hout[(size_t)row * 32 + ty * 2 + 1] = o1;
            }
        }
    } else {
        __syncthreads();            // rowsum init visible
        float fj[8], bj[8];
#pragma unroll
        for (int j = 0; j < 8; j++) { fj[j] = fcW[ty * 8 + j]; bj[j] = bias[ty * 8 + j]; }
#pragma unroll
        for (int r = 0; r < 4; r++) {
            float s = 0.f;
#pragma unroll
            for (int j = 0; j < 8; j++) s += leaky(acc[r][j] + bj[j]) * fj[j];
            atomicAdd(&rowsum[tx * 4 + r], s);
        }
        __syncthreads();
        if (tid < TM) {
            int row = row0 + tid;
            if (row < n) {
                int g = idx_at(batch, row);
                atomicAdd(&g_gsum[g * REP + (blockIdx.x & (REP - 1))], rowsum[tid]);
            }
        }
    }
}

// ---------------- final: counts via binary search over sorted batch ----------------
__global__ void k_final(const void* __restrict__ batch, const float* __restrict__ fcb,
                        float* __restrict__ out, int n) {
    __shared__ int lb[G + 1];
    int t = threadIdx.x;
    if (t <= G) {
        int lo = 0, hi = n;
        while (lo < hi) {
            int mid = (lo + hi) >> 1;
            if (idx_at(batch, mid) < t) lo = mid + 1; else hi = mid;
        }
        lb[t] = lo;
    }
    __syncthreads();
    if (t < G) {
        float s = 0.f;
#pragma unroll
        for (int r = 0; r < REP; r++) s += g_gsum[t * REP + r];
        float c = (float)(lb[t + 1] - lb[t]);
        if (c < 1.f) c = 1.f;
        out[t] = s / c + fcb[0];
    }
}

// ---------------- launch ----------------
extern "C" void kernel_launch(void* const* d_in, const int* in_sizes, int n_in,
                              void* d_out, int out_size) {
    const float* x    = (const float*)d_in[0];
    const void*  ei   = d_in[1];
    const void*  bat  = d_in[2];
    const float* W1   = (const float*)d_in[3];
    const float* b1   = (const float*)d_in[4];
    const float* W2   = (const float*)d_in[5];
    const float* b2   = (const float*)d_in[6];
    const float* fcW  = (const float*)d_in[7];
    const float* fcb  = (const float*)d_in[8];
    float*       out  = (float*)d_out;

    int n = in_sizes[0] / D;
    int e = in_sizes[1] / 2;
    int nb = (n + SCB - 1) / SCB;

    float* h2;
    cudaGetSymbolAddress((void**)&h2, g_h2);

    int tb = 256;
    // CSR build
    k_init<<<(n + tb - 1) / tb, tb>>>((const int*)ei, n);
    k_deg<<<(e + tb - 1) / tb, tb>>>(ei, e);
    k_scan1<<<nb, SCB>>>(n);
    k_scan2<<<1, 128>>>(nb, n);
    k_scan3<<<nb, SCB>>>(n);
    k_fill<<<(e + tb - 1) / tb, tb>>>(ei, e);

    int gblk = (n + TM - 1) / TM;
    // layer 1: h2 = leaky(agg(x)@W1 + b1)
    k_fused<0><<<gblk, 256>>>((const float4*)x, W1, b1, nullptr, nullptr,
                              (float4*)h2, n);
    // layer 2 fused with pooling/fc: gsum += leaky(agg(h2)@W2 + b2) . fcW
    k_fused<1><<<gblk, 256>>>((const float4*)h2, W2, b2, fcW, bat, nullptr, n);

    k_final<<<1, 128>>>(bat, fcb, out, n);
}